// round 7
// baseline (speedup 1.0000x reference)
#include <cuda_runtime.h>
#include <cstdint>

#define BATCH 16
#define NPTS  4096
#define NOUT  1024
#define CIN   256
#define COUT  512
#define KNB   16
#define XOUT_ELEMS (BATCH * NOUT * COUT)   // 8388608
#define FPS_THREADS 512
#define FPS_CTAS 8                          // 2 batches per CTA

// Scratch: device globals (no allocation allowed anywhere).
__device__ float g_h[(size_t)BATCH * NPTS * COUT];   // 128 MB: post-MLP features
__device__ int   g_fid[BATCH * NOUT];                // flat FPS indices into B*N

// ---------------- packed f32x2 helpers (bit-exact per-lane .rn) ----------------
static __device__ __forceinline__ unsigned long long pk2(float a, float b) {
    unsigned long long r;
    asm("mov.b64 %0,{%1,%2};" : "=l"(r) : "f"(a), "f"(b));
    return r;
}
static __device__ __forceinline__ void upk2(unsigned long long v, float& a, float& b) {
    asm("mov.b64 {%0,%1},%2;" : "=f"(a), "=f"(b) : "l"(v));
}
static __device__ __forceinline__ unsigned long long addx2(unsigned long long a, unsigned long long b) {
    unsigned long long r;
    asm("add.rn.f32x2 %0,%1,%2;" : "=l"(r) : "l"(a), "l"(b));
    return r;
}
static __device__ __forceinline__ unsigned long long mulx2(unsigned long long a, unsigned long long b) {
    unsigned long long r;
    asm("mul.rn.f32x2 %0,%1,%2;" : "=l"(r) : "l"(a), "l"(b));
    return r;
}
static __device__ __forceinline__ uint32_t f2tf32(float f) {
    uint32_t r;
    asm("cvt.rna.tf32.f32 %0,%1;" : "=r"(r) : "f"(f));
    return r;
}
static __device__ __forceinline__ void mma_tf32(float* c, const uint32_t* a, const uint32_t* b) {
    asm volatile(
        "mma.sync.aligned.m16n8k8.row.col.f32.tf32.tf32.f32 "
        "{%0,%1,%2,%3},{%4,%5,%6,%7},{%8,%9},{%0,%1,%2,%3};"
        : "+f"(c[0]), "+f"(c[1]), "+f"(c[2]), "+f"(c[3])
        : "r"(a[0]), "r"(a[1]), "r"(a[2]), "r"(a[3]), "r"(b[0]), "r"(b[1]));
}

// ---------------- FPS: one CTA handles TWO batches (latency hiding) ----------------
// Arithmetic/selection bit-identical to the passing R5 kernel per batch:
// dist = ((dx*dx + dy*dy) + dz*dz), all .rn, no FMA contraction; running min;
// first-occurrence argmax via strict-> tracking + lowest-lane/lowest-warp ties.
static __device__ void fps2_block(const float* __restrict__ p, float* __restrict__ out, char* smem)
{
    const int b0 = blockIdx.x * 2;
    float* s_p0 = (float*)smem;                 // 12288 floats (batch b0, xyz)
    float* s_p1 = s_p0 + 3 * NPTS;              // 12288 floats (batch b0+1)
    float* s_rv = s_p1 + 3 * NPTS;              // [2 parity][2 batch][16]
    int*   s_ri = (int*)(s_rv + 64);            // [2 parity][2 batch][16]

    const int t = threadIdx.x, lane = t & 31, warp = t >> 5;
    const float* pb = p + (size_t)b0 * NPTS * 3;
    for (int i = t; i < 3 * NPTS; i += FPS_THREADS) {
        s_p0[i] = pb[i];
        s_p1[i] = pb[3 * NPTS + i];
    }
    __syncthreads();

    // it = 0 outputs (forced index 0)
    if (t < 2) {
        const float* sp = t ? s_p1 : s_p0;
        const int bb = b0 + t;
        g_fid[bb * NOUT] = bb * NPTS;
        float* po = out + (size_t)XOUT_ELEMS + (size_t)(bb * NOUT) * 3;
        po[0] = sp[0]; po[1] = sp[1]; po[2] = sp[2];
    }

    // thread t owns points [t*8, t*8+8) of EACH batch, packed in pairs
    const int base = t * 8;
    unsigned long long Px[2][4], Py[2][4], Pz[2][4];
    float d[2][8];
#pragma unroll
    for (int s = 0; s < 2; ++s) {
        const float* sp = s ? s_p1 : s_p0;
#pragma unroll
        for (int q = 0; q < 4; ++q) {
            const int j0 = base + 2 * q;
            Px[s][q] = pk2(sp[3 * j0 + 0], sp[3 * j0 + 3]);
            Py[s][q] = pk2(sp[3 * j0 + 1], sp[3 * j0 + 4]);
            Pz[s][q] = pk2(sp[3 * j0 + 2], sp[3 * j0 + 5]);
        }
#pragma unroll
        for (int j = 0; j < 8; ++j) d[s][j] = __int_as_float(0x7f800000);  // +inf
    }

    float cx[2], cy[2], cz[2];
    cx[0] = s_p0[0]; cy[0] = s_p0[1]; cz[0] = s_p0[2];
    cx[1] = s_p1[0]; cy[1] = s_p1[1]; cz[1] = s_p1[2];

    for (int it = 1; it < NOUT; ++it) {
        const int buf = it & 1;
        // ---- per-batch: distance update + warp-level argmax, stash per-warp winner ----
#pragma unroll
        for (int s = 0; s < 2; ++s) {
            const unsigned long long nx = pk2(-cx[s], -cx[s]);
            const unsigned long long ny = pk2(-cy[s], -cy[s]);
            const unsigned long long nz = pk2(-cz[s], -cz[s]);
            float best = -1.0f;
            int bi = base;
#pragma unroll
            for (int q = 0; q < 4; ++q) {
                unsigned long long dx = addx2(Px[s][q], nx);
                unsigned long long dy = addx2(Py[s][q], ny);
                unsigned long long dz = addx2(Pz[s][q], nz);
                unsigned long long sq =
                    addx2(addx2(mulx2(dx, dx), mulx2(dy, dy)), mulx2(dz, dz));
                float s0, s1;
                upk2(sq, s0, s1);
                float d0 = fminf(d[s][2 * q], s0);
                float d1 = fminf(d[s][2 * q + 1], s1);
                d[s][2 * q] = d0;
                d[s][2 * q + 1] = d1;
                if (d0 > best) { best = d0; bi = base + 2 * q; }
                if (d1 > best) { best = d1; bi = base + 2 * q + 1; }
            }
            // warp argmax: d >= 0 so float bits are monotonic as u32
            const unsigned bb = __float_as_uint(best);
            const unsigned wm = __reduce_max_sync(0xffffffffu, bb);
            const unsigned msk = __ballot_sync(0xffffffffu, bb == wm);
            const int src = __ffs(msk) - 1;          // lowest lane = lowest point idx
            const int wbi = __shfl_sync(0xffffffffu, bi, src);
            if (lane == 0) {
                s_rv[(buf * 2 + s) * 16 + warp] = __uint_as_float(wm);
                s_ri[(buf * 2 + s) * 16 + warp] = wbi;
            }
        }
        __syncthreads();   // single barrier per iteration (parity buffers avoid WAR race)

        // ---- stage 2: every warp redundantly reduces the 16 warp-candidates ----
        int w[2];
#pragma unroll
        for (int s = 0; s < 2; ++s) {
            const float* rv = s_rv + (buf * 2 + s) * 16;
            const int*   ri = s_ri + (buf * 2 + s) * 16;
            const unsigned v = (lane < 16) ? __float_as_uint(rv[lane]) : 0u;
            const unsigned m2 = __reduce_max_sync(0xffffffffu, v);
            const unsigned e2 = __ballot_sync(0xffffffffu, (v == m2) && (lane < 16));
            const int s2 = __ffs(e2) - 1;            // lowest warp = lowest point idx
            const int ril = (lane < 16) ? ri[lane] : 0;
            w[s] = __shfl_sync(0xffffffffu, ril, s2);
        }
        // new centers (smem broadcast reads)
        cx[0] = s_p0[3 * w[0]]; cy[0] = s_p0[3 * w[0] + 1]; cz[0] = s_p0[3 * w[0] + 2];
        cx[1] = s_p1[3 * w[1]]; cy[1] = s_p1[3 * w[1] + 1]; cz[1] = s_p1[3 * w[1] + 2];

        // stream outputs (fire-and-forget stores by 2 threads)
        if (t < 2) {
            const int s = t, bb = b0 + s, wi = w[s];
            const float* sp = s ? s_p1 : s_p0;
            g_fid[bb * NOUT + it] = bb * NPTS + wi;
            float* po = out + (size_t)XOUT_ELEMS + (size_t)(bb * NOUT + it) * 3;
            po[0] = sp[3 * wi]; po[1] = sp[3 * wi + 1]; po[2] = sp[3 * wi + 2];
        }
    }
}

// ---------------- GEMM: h = ReLU(BN(x @ W^T + b)), tf32 mma.sync ----------------
// CTA tile 128x128, 512 threads = 16 warps (4x4), warp tile 32x32, K-chunk 32.
static __device__ void gemm_block(const float* __restrict__ x, const float* __restrict__ Wm,
                                  const float* __restrict__ bias, const float* __restrict__ gamma,
                                  const float* __restrict__ beta, const float* __restrict__ mean,
                                  const float* __restrict__ var, int g, char* smem)
{
    float* As   = (float*)smem;        // 128 x 36 (padded)
    float* Bs   = As + 128 * 36;       // 128 x 36
    float* s_sc = Bs + 128 * 36;       // 128
    float* s_sh = s_sc + 128;          // 128

    const int m0 = (g >> 2) * 128;     // 512 M-tiles
    const int n0 = (g & 3) * 128;      // 4 N-tiles
    const int t = threadIdx.x, lane = t & 31, warp = t >> 5;
    const int wm = warp >> 2, wn = warp & 3;
    const int grp = lane >> 2, tg = lane & 3;

    if (t < 128) {
        const int c = n0 + t;
        const float sc = gamma[c] * rsqrtf(var[c] + 1e-5f);
        s_sc[t] = sc;
        s_sh[t] = (bias[c] - mean[c]) * sc + beta[c];
    }

    float acc[2][4][4];
#pragma unroll
    for (int mt = 0; mt < 2; ++mt)
#pragma unroll
        for (int nt = 0; nt < 4; ++nt)
#pragma unroll
            for (int j = 0; j < 4; ++j) acc[mt][nt][j] = 0.0f;

    for (int kc = 0; kc < CIN; kc += 32) {
#pragma unroll
        for (int r = 0; r < 2; ++r) {
            const int fi = t + r * 512;
            const int row = fi >> 3, c4 = (fi & 7) * 4;
            const float4 va = *(const float4*)(x + (size_t)(m0 + row) * CIN + kc + c4);
            *(float4*)(As + row * 36 + c4) = va;
            const float4 vb = *(const float4*)(Wm + (size_t)(n0 + row) * CIN + kc + c4);
            *(float4*)(Bs + row * 36 + c4) = vb;
        }
        __syncthreads();
#pragma unroll
        for (int ks = 0; ks < 4; ++ks) {
            const int kb = ks * 8;
            uint32_t a[2][4], bf[4][2];
#pragma unroll
            for (int mt = 0; mt < 2; ++mt) {
                const float* ap = As + (wm * 32 + mt * 16 + grp) * 36 + kb + tg;
                a[mt][0] = f2tf32(ap[0]);
                a[mt][1] = f2tf32(ap[8 * 36]);
                a[mt][2] = f2tf32(ap[4]);
                a[mt][3] = f2tf32(ap[8 * 36 + 4]);
            }
#pragma unroll
            for (int nt = 0; nt < 4; ++nt) {
                const float* bp = Bs + (wn * 32 + nt * 8 + grp) * 36 + kb + tg;
                bf[nt][0] = f2tf32(bp[0]);
                bf[nt][1] = f2tf32(bp[4]);
            }
#pragma unroll
            for (int mt = 0; mt < 2; ++mt)
#pragma unroll
                for (int nt = 0; nt < 4; ++nt) mma_tf32(acc[mt][nt], a[mt], bf[nt]);
        }
        __syncthreads();
    }

    // epilogue: BN(eval) + ReLU, write to g_h
#pragma unroll
    for (int mt = 0; mt < 2; ++mt) {
#pragma unroll
        for (int nt = 0; nt < 4; ++nt) {
#pragma unroll
            for (int j = 0; j < 4; ++j) {
                const int row = m0 + wm * 32 + mt * 16 + grp + (j >> 1) * 8;
                const int lc = wn * 32 + nt * 8 + tg * 2 + (j & 1);
                float v = acc[mt][nt][j] * s_sc[lc] + s_sh[lc];
                v = fmaxf(v, 0.0f);
                g_h[(size_t)row * COUT + n0 + lc] = v;
            }
        }
    }
}

// ---------------- fused kernel: FPS blocks 0..7 (wave 1) + GEMM blocks ----------------
__global__ __launch_bounds__(FPS_THREADS)
void fused_kernel(const float* __restrict__ x, const float* __restrict__ p,
                  const float* __restrict__ Wm, const float* __restrict__ bias,
                  const float* __restrict__ gamma, const float* __restrict__ beta,
                  const float* __restrict__ mean, const float* __restrict__ var,
                  float* __restrict__ out)
{
    extern __shared__ char smem[];
    if (blockIdx.x < FPS_CTAS)
        fps2_block(p, out, smem);
    else
        gemm_block(x, Wm, bias, gamma, beta, mean, var, (int)blockIdx.x - FPS_CTAS, smem);
}

// ---------------- gather + maxpool over K neighbors ----------------
// sid_euc is int32 in practice (JAX x64 disabled); deterministic int64 sniff kept.
__global__ __launch_bounds__(128)
void gather_kernel(const int* __restrict__ sid32, float* __restrict__ out)
{
    __shared__ int s_idx[KNB];
    const int r = blockIdx.x;     // output row in [0, B*n)
    const int t = threadIdx.x;    // channel group: float4 at col t*4
    if (t < KNB) {
        const bool is64 = (sid32[1] == 0) && (sid32[3] == 0) &&
                          (sid32[5] == 0) && (sid32[7] == 0);
        const int fidf = g_fid[r];
        s_idx[t] = is64 ? sid32[((size_t)fidf * KNB + t) * 2]
                        : sid32[(size_t)fidf * KNB + t];
    }
    __syncthreads();
    float4 m = *(const float4*)(g_h + (size_t)s_idx[0] * COUT + t * 4);
#pragma unroll
    for (int k = 1; k < KNB; ++k) {
        const float4 v = *(const float4*)(g_h + (size_t)s_idx[k] * COUT + t * 4);
        m.x = fmaxf(m.x, v.x);
        m.y = fmaxf(m.y, v.y);
        m.z = fmaxf(m.z, v.z);
        m.w = fmaxf(m.w, v.w);
    }
    *(float4*)(out + (size_t)r * COUT + t * 4) = m;
}

// ---------------- launch ----------------
// FPS needs 98304 (points) + 512 (reduction) bytes; bumped to 118 KB so that
// 2 CTAs don't fit in a 228 KB SM -> 1 CTA/SM, keeping FPS SMs exclusive.
#define FUSED_SMEM 120832

extern "C" void kernel_launch(void* const* d_in, const int* in_sizes, int n_in,
                              void* d_out, int out_size)
{
    (void)in_sizes; (void)n_in; (void)out_size;
    const float* x      = (const float*)d_in[0];
    const float* p      = (const float*)d_in[1];
    const int*   sid    = (const int*)d_in[2];   // int32 (x64 disabled in JAX)
    // d_in[3] = tid_euc (unused by reference)
    const float* W      = (const float*)d_in[4];
    const float* bias   = (const float*)d_in[5];
    const float* gamma  = (const float*)d_in[6];
    const float* beta   = (const float*)d_in[7];
    const float* mean   = (const float*)d_in[8];
    const float* var    = (const float*)d_in[9];
    float* out = (float*)d_out;

    // Opt-in to >48KB dynamic smem (host-side, idempotent, capture-legal).
    cudaFuncSetAttribute(fused_kernel, cudaFuncAttributeMaxDynamicSharedMemorySize, FUSED_SMEM);

    const int gemm_blocks = (BATCH * NPTS / 128) * (COUT / 128);  // 2048
    fused_kernel<<<FPS_CTAS + gemm_blocks, FPS_THREADS, FUSED_SMEM>>>(
        x, p, W, bias, gamma, beta, mean, var, out);
    gather_kernel<<<BATCH * NOUT, 128>>>(sid, out);
}

// round 8
// speedup vs baseline: 2.2850x; 2.2850x over previous
#include <cuda_runtime.h>
#include <cstdint>

#define BATCH 16
#define NPTS  4096
#define NOUT  1024
#define CIN   256
#define COUT  512
#define KNB   16
#define XOUT_ELEMS (BATCH * NOUT * COUT)   // 8388608
#define FPS_THREADS 512

// Scratch: device globals (no allocation allowed anywhere).
__device__ float g_h[(size_t)BATCH * NPTS * COUT];   // 128 MB: post-MLP features
__device__ int   g_fid[BATCH * NOUT];                // flat FPS indices into B*N

// ---------------- packed f32x2 helpers (bit-exact per-lane .rn) ----------------
static __device__ __forceinline__ unsigned long long pk2(float a, float b) {
    unsigned long long r;
    asm("mov.b64 %0,{%1,%2};" : "=l"(r) : "f"(a), "f"(b));
    return r;
}
static __device__ __forceinline__ void upk2(unsigned long long v, float& a, float& b) {
    asm("mov.b64 {%0,%1},%2;" : "=f"(a), "=f"(b) : "l"(v));
}
static __device__ __forceinline__ unsigned long long addx2(unsigned long long a, unsigned long long b) {
    unsigned long long r;
    asm("add.rn.f32x2 %0,%1,%2;" : "=l"(r) : "l"(a), "l"(b));
    return r;
}
static __device__ __forceinline__ unsigned long long mulx2(unsigned long long a, unsigned long long b) {
    unsigned long long r;
    asm("mul.rn.f32x2 %0,%1,%2;" : "=l"(r) : "l"(a), "l"(b));
    return r;
}
static __device__ __forceinline__ uint32_t f2tf32(float f) {
    uint32_t r;
    asm("cvt.rna.tf32.f32 %0,%1;" : "=r"(r) : "f"(f));
    return r;
}
static __device__ __forceinline__ void mma_tf32(float* c, const uint32_t* a, const uint32_t* b) {
    asm volatile(
        "mma.sync.aligned.m16n8k8.row.col.f32.tf32.tf32.f32 "
        "{%0,%1,%2,%3},{%4,%5,%6,%7},{%8,%9},{%0,%1,%2,%3};"
        : "+f"(c[0]), "+f"(c[1]), "+f"(c[2]), "+f"(c[3])
        : "r"(a[0]), "r"(a[1]), "r"(a[2]), "r"(a[3]), "r"(b[0]), "r"(b[1]));
}

// ---------------- FPS: one CTA (512 threads) per batch ----------------
// Arithmetic/selection bit-identical to the passing R5 kernel:
// dist = ((dx*dx + dy*dy) + dz*dz), all .rn, no FMA contraction; running min;
// first-occurrence argmax via strict-> scan + lowest-lane/lowest-warp ties.
// R7 change: SINGLE barrier per iteration. Per-warp candidates go to a
// parity-double-buffered smem slab; after one __syncthreads every warp
// redundantly reduces all 16 candidates (no second barrier, no rebroadcast).
// WAR safety: a warp can only overwrite buffer `q` after passing the barrier
// of the NEXT iteration, which requires all warps done reading buffer `q`.
static __device__ void fps_block(const float* __restrict__ p, float* __restrict__ out, char* smem)
{
    const int b = blockIdx.x;
    float* s_p  = (float*)smem;                 // 4096*3 floats, interleaved xyz
    float* s_rv = s_p + 3 * NPTS;               // [2 parity][16]
    int*   s_ri = (int*)(s_rv + 32);            // [2 parity][16]

    const float* pb = p + (size_t)b * NPTS * 3;
    const int t = threadIdx.x, lane = t & 31, warp = t >> 5;
    for (int i = t; i < 3 * NPTS; i += FPS_THREADS) s_p[i] = pb[i];
    __syncthreads();

    // it = 0 output (forced index 0)
    if (t == 0) {
        g_fid[b * NOUT] = b * NPTS;
        float* po = out + (size_t)XOUT_ELEMS + (size_t)(b * NOUT) * 3;
        po[0] = s_p[0]; po[1] = s_p[1]; po[2] = s_p[2];
    }

    // thread t owns points [t*8, t*8+8), packed in pairs
    const int base = t * 8;
    unsigned long long Px[4], Py[4], Pz[4];
    float d[8];
#pragma unroll
    for (int q = 0; q < 4; ++q) {
        const int j0 = base + 2 * q;
        Px[q] = pk2(s_p[3 * j0 + 0], s_p[3 * j0 + 3]);
        Py[q] = pk2(s_p[3 * j0 + 1], s_p[3 * j0 + 4]);
        Pz[q] = pk2(s_p[3 * j0 + 2], s_p[3 * j0 + 5]);
    }
#pragma unroll
    for (int j = 0; j < 8; ++j) d[j] = __int_as_float(0x7f800000);  // +inf

    float cx = s_p[0], cy = s_p[1], cz = s_p[2];  // center = point 0

    for (int it = 1; it < NOUT; ++it) {
        const int buf = it & 1;
        const unsigned long long nx = pk2(-cx, -cx);
        const unsigned long long ny = pk2(-cy, -cy);
        const unsigned long long nz = pk2(-cz, -cz);
        float best = -1.0f;
        int bi = base;
#pragma unroll
        for (int q = 0; q < 4; ++q) {
            unsigned long long dx = addx2(Px[q], nx);
            unsigned long long dy = addx2(Py[q], ny);
            unsigned long long dz = addx2(Pz[q], nz);
            unsigned long long sq =
                addx2(addx2(mulx2(dx, dx), mulx2(dy, dy)), mulx2(dz, dz));
            float s0, s1;
            upk2(sq, s0, s1);
            float d0 = fminf(d[2 * q], s0);
            float d1 = fminf(d[2 * q + 1], s1);
            d[2 * q] = d0;
            d[2 * q + 1] = d1;
            if (d0 > best) { best = d0; bi = base + 2 * q; }
            if (d1 > best) { best = d1; bi = base + 2 * q + 1; }
        }
        // warp argmax: d >= 0 so float bits are monotonic as u32
        const unsigned bb = __float_as_uint(best);
        const unsigned wm = __reduce_max_sync(0xffffffffu, bb);
        const unsigned msk = __ballot_sync(0xffffffffu, bb == wm);
        const int src = __ffs(msk) - 1;              // lowest lane = lowest point idx
        const int wbi = __shfl_sync(0xffffffffu, bi, src);
        if (lane == 0) {
            s_rv[buf * 16 + warp] = __uint_as_float(wm);
            s_ri[buf * 16 + warp] = wbi;
        }
        __syncthreads();   // single barrier per iteration

        // every warp redundantly reduces the 16 per-warp candidates
        const float* rv = s_rv + buf * 16;
        const int*   ri = s_ri + buf * 16;
        const unsigned v = (lane < 16) ? __float_as_uint(rv[lane]) : 0u;
        const unsigned m2 = __reduce_max_sync(0xffffffffu, v);
        const unsigned e2 = __ballot_sync(0xffffffffu, (v == m2) && (lane < 16));
        const int s2 = __ffs(e2) - 1;                // lowest warp = lowest point idx
        const int ril = (lane < 16) ? ri[lane] : 0;
        const int w = __shfl_sync(0xffffffffu, ril, s2);

        cx = s_p[3 * w];
        cy = s_p[3 * w + 1];
        cz = s_p[3 * w + 2];

        // stream outputs (fire-and-forget store by thread 0)
        if (t == 0) {
            g_fid[b * NOUT + it] = b * NPTS + w;
            float* po = out + (size_t)XOUT_ELEMS + (size_t)(b * NOUT + it) * 3;
            po[0] = cx; po[1] = cy; po[2] = cz;
        }
    }
}

// ---------------- GEMM: h = ReLU(BN(x @ W^T + b)), tf32 mma.sync ----------------
// CTA tile 128x128, 512 threads = 16 warps (4x4), warp tile 32x32, K-chunk 32.
static __device__ void gemm_block(const float* __restrict__ x, const float* __restrict__ Wm,
                                  const float* __restrict__ bias, const float* __restrict__ gamma,
                                  const float* __restrict__ beta, const float* __restrict__ mean,
                                  const float* __restrict__ var, int g, char* smem)
{
    float* As   = (float*)smem;        // 128 x 36 (padded)
    float* Bs   = As + 128 * 36;       // 128 x 36
    float* s_sc = Bs + 128 * 36;       // 128
    float* s_sh = s_sc + 128;          // 128

    const int m0 = (g >> 2) * 128;     // 512 M-tiles
    const int n0 = (g & 3) * 128;      // 4 N-tiles
    const int t = threadIdx.x, lane = t & 31, warp = t >> 5;
    const int wm = warp >> 2, wn = warp & 3;
    const int grp = lane >> 2, tg = lane & 3;

    if (t < 128) {
        const int c = n0 + t;
        const float sc = gamma[c] * rsqrtf(var[c] + 1e-5f);
        s_sc[t] = sc;
        s_sh[t] = (bias[c] - mean[c]) * sc + beta[c];
    }

    float acc[2][4][4];
#pragma unroll
    for (int mt = 0; mt < 2; ++mt)
#pragma unroll
        for (int nt = 0; nt < 4; ++nt)
#pragma unroll
            for (int j = 0; j < 4; ++j) acc[mt][nt][j] = 0.0f;

    for (int kc = 0; kc < CIN; kc += 32) {
#pragma unroll
        for (int r = 0; r < 2; ++r) {
            const int fi = t + r * 512;
            const int row = fi >> 3, c4 = (fi & 7) * 4;
            const float4 va = *(const float4*)(x + (size_t)(m0 + row) * CIN + kc + c4);
            *(float4*)(As + row * 36 + c4) = va;
            const float4 vb = *(const float4*)(Wm + (size_t)(n0 + row) * CIN + kc + c4);
            *(float4*)(Bs + row * 36 + c4) = vb;
        }
        __syncthreads();
#pragma unroll
        for (int ks = 0; ks < 4; ++ks) {
            const int kb = ks * 8;
            uint32_t a[2][4], bf[4][2];
#pragma unroll
            for (int mt = 0; mt < 2; ++mt) {
                const float* ap = As + (wm * 32 + mt * 16 + grp) * 36 + kb + tg;
                a[mt][0] = f2tf32(ap[0]);
                a[mt][1] = f2tf32(ap[8 * 36]);
                a[mt][2] = f2tf32(ap[4]);
                a[mt][3] = f2tf32(ap[8 * 36 + 4]);
            }
#pragma unroll
            for (int nt = 0; nt < 4; ++nt) {
                const float* bp = Bs + (wn * 32 + nt * 8 + grp) * 36 + kb + tg;
                bf[nt][0] = f2tf32(bp[0]);
                bf[nt][1] = f2tf32(bp[4]);
            }
#pragma unroll
            for (int mt = 0; mt < 2; ++mt)
#pragma unroll
                for (int nt = 0; nt < 4; ++nt) mma_tf32(acc[mt][nt], a[mt], bf[nt]);
        }
        __syncthreads();
    }

    // epilogue: BN(eval) + ReLU, write to g_h
#pragma unroll
    for (int mt = 0; mt < 2; ++mt) {
#pragma unroll
        for (int nt = 0; nt < 4; ++nt) {
#pragma unroll
            for (int j = 0; j < 4; ++j) {
                const int row = m0 + wm * 32 + mt * 16 + grp + (j >> 1) * 8;
                const int lc = wn * 32 + nt * 8 + tg * 2 + (j & 1);
                float v = acc[mt][nt][j] * s_sc[lc] + s_sh[lc];
                v = fmaxf(v, 0.0f);
                g_h[(size_t)row * COUT + n0 + lc] = v;
            }
        }
    }
}

// ---------------- fused kernel: FPS blocks 0..15 (wave 1) + GEMM blocks ----------------
__global__ __launch_bounds__(FPS_THREADS)
void fused_kernel(const float* __restrict__ x, const float* __restrict__ p,
                  const float* __restrict__ Wm, const float* __restrict__ bias,
                  const float* __restrict__ gamma, const float* __restrict__ beta,
                  const float* __restrict__ mean, const float* __restrict__ var,
                  float* __restrict__ out)
{
    extern __shared__ char smem[];
    if (blockIdx.x < 16)
        fps_block(p, out, smem);
    else
        gemm_block(x, Wm, bias, gamma, beta, mean, var, (int)blockIdx.x - 16, smem);
}

// ---------------- gather + maxpool over K neighbors ----------------
// sid_euc is int32 in practice (JAX x64 disabled); deterministic int64 sniff kept.
__global__ __launch_bounds__(128)
void gather_kernel(const int* __restrict__ sid32, float* __restrict__ out)
{
    __shared__ int s_idx[KNB];
    const int r = blockIdx.x;     // output row in [0, B*n)
    const int t = threadIdx.x;    // channel group: float4 at col t*4
    if (t < KNB) {
        const bool is64 = (sid32[1] == 0) && (sid32[3] == 0) &&
                          (sid32[5] == 0) && (sid32[7] == 0);
        const int fidf = g_fid[r];
        s_idx[t] = is64 ? sid32[((size_t)fidf * KNB + t) * 2]
                        : sid32[(size_t)fidf * KNB + t];
    }
    __syncthreads();
    float4 m = *(const float4*)(g_h + (size_t)s_idx[0] * COUT + t * 4);
#pragma unroll
    for (int k = 1; k < KNB; ++k) {
        const float4 v = *(const float4*)(g_h + (size_t)s_idx[k] * COUT + t * 4);
        m.x = fmaxf(m.x, v.x);
        m.y = fmaxf(m.y, v.y);
        m.z = fmaxf(m.z, v.z);
        m.w = fmaxf(m.w, v.w);
    }
    *(float4*)(out + (size_t)r * COUT + t * 4) = m;
}

// ---------------- launch ----------------
// 53.5 KB: FPS fits (49152 pts + 256 reduce), GEMM fits (37888), and GEMM
// keeps 4 CTAs/SM (4 x 53504 = 214016 < 228KB, 4 x 512 = 2048 threads).
#define FUSED_SMEM 53504

extern "C" void kernel_launch(void* const* d_in, const int* in_sizes, int n_in,
                              void* d_out, int out_size)
{
    (void)in_sizes; (void)n_in; (void)out_size;
    const float* x      = (const float*)d_in[0];
    const float* p      = (const float*)d_in[1];
    const int*   sid    = (const int*)d_in[2];   // int32 (x64 disabled in JAX)
    // d_in[3] = tid_euc (unused by reference)
    const float* W      = (const float*)d_in[4];
    const float* bias   = (const float*)d_in[5];
    const float* gamma  = (const float*)d_in[6];
    const float* beta   = (const float*)d_in[7];
    const float* mean   = (const float*)d_in[8];
    const float* var    = (const float*)d_in[9];
    float* out = (float*)d_out;

    // Opt-in to >48KB dynamic smem (host-side, idempotent, capture-legal).
    cudaFuncSetAttribute(fused_kernel, cudaFuncAttributeMaxDynamicSharedMemorySize, FUSED_SMEM);

    const int gemm_blocks = (BATCH * NPTS / 128) * (COUT / 128);  // 2048
    fused_kernel<<<16 + gemm_blocks, FPS_THREADS, FUSED_SMEM>>>(
        x, p, W, bias, gamma, beta, mean, var, out);
    gather_kernel<<<BATCH * NOUT, 128>>>(sid, out);
}